// round 3
// baseline (speedup 1.0000x reference)
#include <cuda_runtime.h>
#include <cuda_bf16.h>

// SSIM loss: fused separable 11x11 Gaussian SSIM + in-kernel final reduction.
// imgs (16,3,512,512) fp32 -> scalar fp32 = 1 - mean(ssim_map).

#define IMG     512
#define NIMG    48
#define TX      64
#define TY      32
#define HALO    5
#define IW      74              // TX + 10
#define IWP     75              // padded stride
#define IH      42              // TY + 10
#define HP      65              // H row stride
#define HCH     (IH*HP)         // 2730
#define NT      384
#define GXB     (IMG/TX)        // 8
#define GYB     (IMG/TY)        // 16
#define ZSPLIT  3
#define ZCHUNK  (NIMG/ZSPLIT)   // 16
#define NBLOCKS (GXB*GYB*NIMG)  // 6144

#define W0 0.00102838f
#define W1 0.00759876f
#define W2 0.03600077f
#define W3 0.10936070f
#define W4 0.21300554f
#define W5 0.26601173f

__device__ float    g_partials[NBLOCKS];
__device__ unsigned g_sync = 0;

// Vertical blur strip of LEN output rows + pointwise SSIM, gather form.
template<int LEN>
__device__ __forceinline__ float ssim_vstrip(const float* __restrict__ q)
{
    const float Wt[11] = {W0, W1, W2, W3, W4, W5, W4, W3, W2, W1, W0};
    float b0[LEN], b1[LEN], b2[LEN], b3[LEN], b4[LEN];
    #pragma unroll
    for (int o = 0; o < LEN; o++) { b0[o]=0.f; b1[o]=0.f; b2[o]=0.f; b3[o]=0.f; b4[o]=0.f; }

    #pragma unroll
    for (int e = 0; e < LEN + 10; e++) {
        float f0 = q[0*HCH + e*HP];
        float f1 = q[1*HCH + e*HP];
        float f2 = q[2*HCH + e*HP];
        float f3 = q[3*HCH + e*HP];
        float f4 = q[4*HCH + e*HP];
        #pragma unroll
        for (int o = 0; o < LEN; o++) {
            if (e - o >= 0 && e - o < 11) {
                const float w = Wt[e - o];
                b0[o] = fmaf(w, f0, b0[o]);
                b1[o] = fmaf(w, f1, b1[o]);
                b2[o] = fmaf(w, f2, b2[o]);
                b3[o] = fmaf(w, f3, b3[o]);
                b4[o] = fmaf(w, f4, b4[o]);
            }
        }
    }

    const float C1 = 0.01f * 0.01f;
    const float C2 = 0.03f * 0.03f;
    float acc = 0.f;
    #pragma unroll
    for (int o = 0; o < LEN; o++) {
        float mu1 = b0[o], mu2 = b1[o];
        float mu1sq = mu1 * mu1;
        float mu2sq = mu2 * mu2;
        float mu12  = mu1 * mu2;
        float sg1  = b2[o] - mu1sq;
        float sg2  = b3[o] - mu2sq;
        float sg12 = b4[o] - mu12;
        float num = (2.0f * mu12 + C1) * (2.0f * sg12 + C2);
        float den = (mu1sq + mu2sq + C1) * (sg1 + sg2 + C2);
        acc += __fdividef(num, den);
    }
    return acc;
}

__global__ __launch_bounds__(NT, 2)
void ssim_tile_kernel(const float* __restrict__ img1,
                      const float* __restrict__ img2,
                      float* __restrict__ out,
                      int zoff)
{
    extern __shared__ float smem[];
    float* s1 = smem;               // [IH][IWP]
    float* s2 = s1 + IH * IWP;
    float* H  = s2 + IH * IWP;      // [5][IH][HP]

    const int tid = threadIdx.x;
    const int bz  = blockIdx.z + zoff;
    const float* base1 = img1 + (size_t)bz * IMG * IMG;
    const float* base2 = img2 + (size_t)bz * IMG * IMG;

    const int gx0 = blockIdx.x * TX - HALO;
    const int gy0 = blockIdx.y * TY - HALO;

    const float Wt[11] = {W0, W1, W2, W3, W4, W5, W4, W3, W2, W1, W0};

    // ---- stage 0: load raw tiles, zero-padded ----
    for (int idx = tid; idx < IH * IW; idx += NT) {
        int r = idx / IW;
        int c = idx - r * IW;
        int gy = gy0 + r;
        int gx = gx0 + c;
        bool ok = ((unsigned)gy < (unsigned)IMG) && ((unsigned)gx < (unsigned)IMG);
        int g = gy * IMG + gx;
        s1[r * IWP + c] = ok ? __ldg(base1 + g) : 0.0f;
        s2[r * IWP + c] = ok ? __ldg(base2 + g) : 0.0f;
    }
    __syncthreads();

    // ---- pass 1: horizontal blur of (x, y, x2, y2, xy), strips of 8 cols ----
    if (tid < IH * (TX / 8)) {
        int row = tid % IH;
        int cs  = (tid / IH) * 8;
        const float* p1 = s1 + row * IWP + cs;
        const float* p2 = s2 + row * IWP + cs;

        float a0[8], a1[8], a2[8], a3[8], a4[8];
        #pragma unroll
        for (int o = 0; o < 8; o++) { a0[o]=0.f; a1[o]=0.f; a2[o]=0.f; a3[o]=0.f; a4[o]=0.f; }

        #pragma unroll
        for (int e = 0; e < 18; e++) {
            float x = p1[e];
            float y = p2[e];
            float xx = x * x;
            float yy = y * y;
            float xy = x * y;
            #pragma unroll
            for (int o = 0; o < 8; o++) {
                if (e - o >= 0 && e - o < 11) {
                    const float w = Wt[e - o];
                    a0[o] = fmaf(w, x,  a0[o]);
                    a1[o] = fmaf(w, y,  a1[o]);
                    a2[o] = fmaf(w, xx, a2[o]);
                    a3[o] = fmaf(w, yy, a3[o]);
                    a4[o] = fmaf(w, xy, a4[o]);
                }
            }
        }
        float* hp = H + row * HP + cs;
        #pragma unroll
        for (int o = 0; o < 8; o++) {
            hp[0*HCH + o] = a0[o];
            hp[1*HCH + o] = a1[o];
            hp[2*HCH + o] = a2[o];
            hp[3*HCH + o] = a3[o];
            hp[4*HCH + o] = a4[o];
        }
    }
    __syncthreads();

    // ---- pass 2: vertical blur + SSIM; 384 strips = 64 cols x {6,6,6,6,4,4} rows ----
    float acc;
    {
        int col = tid & (TX - 1);
        int seg = tid >> 6;                 // warp-uniform
        if (seg < 4) {
            acc = ssim_vstrip<6>(H + (seg * 6) * HP + col);
        } else {
            acc = ssim_vstrip<4>(H + (24 + (seg - 4) * 4) * HP + col);
        }
    }

    // ---- block reduction ----
    #pragma unroll
    for (int off = 16; off > 0; off >>= 1)
        acc += __shfl_xor_sync(0xFFFFFFFFu, acc, off);

    __shared__ float warpsum[NT / 32];
    if ((tid & 31) == 0) warpsum[tid >> 5] = acc;
    __syncthreads();

    __shared__ bool is_last;
    if (tid == 0) {
        float s = 0.f;
        #pragma unroll
        for (int i = 0; i < NT / 32; i++) s += warpsum[i];
        int bid = blockIdx.x + GXB * (blockIdx.y + GYB * bz);
        g_partials[bid] = s;
        __threadfence();
        unsigned prev = atomicAdd(&g_sync, 1u);
        is_last = (prev == NBLOCKS - 1);
    }
    __syncthreads();

    // ---- last block: deterministic final reduction ----
    if (is_last) {
        __threadfence();
        __shared__ double sd[NT];
        double s = 0.0;
        #pragma unroll
        for (int k = 0; k < NBLOCKS / NT; k++)
            s += (double)g_partials[tid + k * NT];
        sd[tid] = s;
        __syncthreads();
        if (tid < 128) sd[tid] += sd[tid + 128] + sd[tid + 256];
        __syncthreads();
        #pragma unroll
        for (int st = 64; st > 0; st >>= 1) {
            if (tid < st) sd[tid] += sd[tid + st];
            __syncthreads();
        }
        if (tid == 0) {
            const double N = 16.0 * 3.0 * 512.0 * 512.0;
            out[0] = (float)(1.0 - sd[0] / N);
            g_sync = 0;   // reset for next graph replay
        }
    }
}

extern "C" void kernel_launch(void* const* d_in, const int* in_sizes, int n_in,
                              void* d_out, int out_size)
{
    const float* img1 = (const float*)d_in[0];
    const float* img2 = (const float*)d_in[1];
    float* out = (float*)d_out;

    const int smem_bytes = (2 * IH * IWP + 5 * IH * HP) * (int)sizeof(float); // 79800
    cudaFuncSetAttribute(ssim_tile_kernel,
                         cudaFuncAttributeMaxDynamicSharedMemorySize, smem_bytes);

    // 3 launches so ncu's "-s 5 -c 1" lands on a tile-kernel launch.
    dim3 grid(GXB, GYB, ZCHUNK);
    for (int z = 0; z < ZSPLIT; z++)
        ssim_tile_kernel<<<grid, NT, smem_bytes>>>(img1, img2, out, z * ZCHUNK);
}

// round 4
// speedup vs baseline: 1.3261x; 1.3261x over previous
#include <cuda_runtime.h>
#include <cstdint>

// SSIM loss: fused separable 11x11 Gaussian SSIM, f32x2-packed, smem-union.
// imgs (16,3,512,512) fp32 -> scalar fp32 = 1 - mean(ssim_map).

#define IMG     512
#define NIMG    48
#define TX      64
#define TY      32
#define IW      74              // TX + 10
#define RAWP    75              // raw pair-row stride (bank: deg<=2)
#define IH      42              // TY + 10
#define HS      65              // H row stride (pairs or floats)
#define NT      352             // 11 warps
#define GXB     8
#define GYB     16
#define NBLOCKS (GXB*GYB*NIMG)  // 6144
#define SMEM_FLOATS 13650       // 54600 bytes

#define W0f 0.00102838f
#define W1f 0.00759876f
#define W2f 0.03600077f
#define W3f 0.10936070f
#define W4f 0.21300554f
#define W5f 0.26601173f

__device__ float    g_partials[NBLOCKS];
__device__ unsigned g_sync = 0;

__device__ __forceinline__ constexpr float WT(int d) {
    return (d==0||d==10) ? W0f : (d==1||d==9) ? W1f : (d==2||d==8) ? W2f :
           (d==3||d==7)  ? W3f : (d==4||d==6) ? W4f : (d==5) ? W5f : 0.0f;
}
__device__ __forceinline__ uint64_t bc(float w) {
    unsigned u = __float_as_uint(w);
    return ((uint64_t)u << 32) | u;
}
__device__ __forceinline__ uint64_t f2mul(uint64_t a, uint64_t b) {
    uint64_t r; asm("mul.rn.f32x2 %0,%1,%2;" : "=l"(r) : "l"(a), "l"(b)); return r;
}
__device__ __forceinline__ void f2fma(uint64_t& d, uint64_t a, uint64_t b) {
    asm("fma.rn.f32x2 %0,%1,%2,%0;" : "+l"(d) : "l"(a), "l"(b));
}
__device__ __forceinline__ float lo32(uint64_t u) { return __uint_as_float((unsigned)u); }
__device__ __forceinline__ float hi32(uint64_t u) { return __uint_as_float((unsigned)(u >> 32)); }

// Vertical blur strip of LEN rows + pointwise SSIM.
// H planes: H4 scalar @S[0], H23 pairs @S[2730], H01 pairs @S[8190]; row stride HS.
template<int LEN>
__device__ __forceinline__ float vstrip(const float* __restrict__ S, int rs, int col,
                                        const uint64_t (&Wb)[6])
{
    const float*    H4  = S;
    const uint64_t* H23 = (const uint64_t*)(S + 2730);
    const uint64_t* H01 = (const uint64_t*)(S + 8190);
    const int base = rs * HS + col;

    uint64_t b01[LEN], b23[LEN]; float b4[LEN];
    #pragma unroll
    for (int o = 0; o < LEN; o++) { b01[o] = 0ull; b23[o] = 0ull; b4[o] = 0.f; }

    #pragma unroll
    for (int e = 0; e < LEN + 10; e++) {
        uint64_t f01 = H01[base + e * HS];
        uint64_t f23 = H23[base + e * HS];
        float    f4  = H4 [base + e * HS];
        #pragma unroll
        for (int o = 0; o < LEN; o++) {
            const int d = e - o;
            if (d >= 0 && d < 11) {
                const int wi = (d < 6) ? d : 10 - d;
                f2fma(b01[o], Wb[wi], f01);
                f2fma(b23[o], Wb[wi], f23);
                b4[o] = fmaf(WT(d), f4, b4[o]);
            }
        }
    }

    const float C1 = 1e-4f, C2 = 9e-4f;
    float acc = 0.f;
    #pragma unroll
    for (int o = 0; o < LEN; o++) {
        float mu1 = lo32(b01[o]), mu2 = hi32(b01[o]);
        float exx = lo32(b23[o]), eyy = hi32(b23[o]);
        float mu1sq = mu1 * mu1, mu2sq = mu2 * mu2, mu12 = mu1 * mu2;
        float sg1 = exx - mu1sq, sg2 = eyy - mu2sq, sg12 = b4[o] - mu12;
        float num = (2.0f * mu12 + C1) * (2.0f * sg12 + C2);
        float den = (mu1sq + mu2sq + C1) * (sg1 + sg2 + C2);
        acc += __fdividef(num, den);
    }
    return acc;
}

__global__ __launch_bounds__(NT, 3)
void ssim_kernel(const float* __restrict__ img1,
                 const float* __restrict__ img2,
                 float* __restrict__ out)
{
    extern __shared__ float S[];
    const int tid = threadIdx.x;
    const int bz  = blockIdx.z;
    const float* ib1 = img1 + (size_t)bz * IMG * IMG;
    const float* ib2 = img2 + (size_t)bz * IMG * IMG;
    const int gx0 = blockIdx.x * TX - 5;
    const int gy0 = blockIdx.y * TY - 5;

    const uint64_t Wb[6] = { bc(W0f), bc(W1f), bc(W2f), bc(W3f), bc(W4f), bc(W5f) };

    // ---- stage 0: load raw (x,y) pairs into smem, zero-padded ----
    float2* raw = (float2*)S;
    for (int idx = tid; idx < IH * IW; idx += NT) {
        int r = idx / IW;
        int c = idx - r * IW;
        int gy = gy0 + r;
        int gx = gx0 + c;
        bool ok = ((unsigned)gy < (unsigned)IMG) & ((unsigned)gx < (unsigned)IMG);
        int g = gy * IMG + gx;
        float x = ok ? __ldg(ib1 + g) : 0.0f;
        float y = ok ? __ldg(ib2 + g) : 0.0f;
        raw[r * RAWP + c] = make_float2(x, y);
    }
    __syncthreads();

    // ---- pass 1: horizontal blur of 5 channels, strips of 8 cols ----
    uint64_t a01[8], a23[8]; float a4[8];
    const bool p1act = (tid < IH * 8);
    int p1row = 0, p1cs = 0;
    if (p1act) {
        p1row = tid % IH;
        p1cs  = (tid / IH) * 8;
        const uint64_t* rp = (const uint64_t*)S + p1row * RAWP + p1cs;
        #pragma unroll
        for (int o = 0; o < 8; o++) { a01[o] = 0ull; a23[o] = 0ull; a4[o] = 0.f; }
        #pragma unroll
        for (int e = 0; e < 18; e++) {
            uint64_t xy = rp[e];
            uint64_t sq = f2mul(xy, xy);
            float   pxy = lo32(xy) * hi32(xy);
            #pragma unroll
            for (int o = 0; o < 8; o++) {
                const int d = e - o;
                if (d >= 0 && d < 11) {
                    const int wi = (d < 6) ? d : 10 - d;
                    f2fma(a01[o], Wb[wi], xy);
                    f2fma(a23[o], Wb[wi], sq);
                    a4[o] = fmaf(WT(d), pxy, a4[o]);
                }
            }
        }
    }
    __syncthreads();            // all raw reads complete before H overwrites raw
    if (p1act) {
        float*    H4  = S;
        uint64_t* H23 = (uint64_t*)(S + 2730);
        uint64_t* H01 = (uint64_t*)(S + 8190);
        const int hb = p1row * HS + p1cs;
        #pragma unroll
        for (int o = 0; o < 8; o++) {
            H01[hb + o] = a01[o];
            H23[hb + o] = a23[o];
            H4 [hb + o] = a4[o];
        }
    }
    __syncthreads();

    // ---- pass 2: vertical blur + SSIM; 320 strips = 64 cols x {7,7,6,6,6} ----
    float acc = 0.f;
    {
        const int col = tid & 63;
        const int seg = tid >> 6;           // warp-uniform
        if (seg < 2)      acc = vstrip<7>(S, seg * 7, col, Wb);
        else if (seg < 5) acc = vstrip<6>(S, 14 + (seg - 2) * 6, col, Wb);
    }

    // ---- block reduction ----
    #pragma unroll
    for (int off = 16; off > 0; off >>= 1)
        acc += __shfl_xor_sync(0xFFFFFFFFu, acc, off);

    __shared__ float warpsum[NT / 32];
    if ((tid & 31) == 0) warpsum[tid >> 5] = acc;
    __syncthreads();

    __shared__ bool is_last;
    if (tid == 0) {
        float s = 0.f;
        #pragma unroll
        for (int i = 0; i < NT / 32; i++) s += warpsum[i];
        int bid = blockIdx.x + GXB * (blockIdx.y + GYB * bz);
        g_partials[bid] = s;
        __threadfence();
        unsigned prev = atomicAdd(&g_sync, 1u);
        is_last = (prev == NBLOCKS - 1);
    }
    __syncthreads();

    // ---- last block: deterministic final reduction ----
    if (is_last) {
        __threadfence();
        __shared__ double sd[NT];
        double s = 0.0;
        for (int k = tid; k < NBLOCKS; k += NT)
            s += (double)g_partials[k];
        sd[tid] = s;
        __syncthreads();
        if (tid < 96) sd[tid] += sd[tid + 256];
        __syncthreads();
        #pragma unroll
        for (int st = 128; st > 0; st >>= 1) {
            if (tid < st) sd[tid] += sd[tid + st];
            __syncthreads();
        }
        if (tid == 0) {
            const double N = 16.0 * 3.0 * 512.0 * 512.0;
            out[0] = (float)(1.0 - sd[0] / N);
            g_sync = 0;     // reset for next graph replay
        }
    }
}

extern "C" void kernel_launch(void* const* d_in, const int* in_sizes, int n_in,
                              void* d_out, int out_size)
{
    const float* img1 = (const float*)d_in[0];
    const float* img2 = (const float*)d_in[1];
    float* out = (float*)d_out;

    const int smem_bytes = SMEM_FLOATS * (int)sizeof(float);   // 54600
    cudaFuncSetAttribute(ssim_kernel,
                         cudaFuncAttributeMaxDynamicSharedMemorySize, smem_bytes);

    dim3 grid(GXB, GYB, NIMG);
    ssim_kernel<<<grid, NT, smem_bytes>>>(img1, img2, out);
}

// round 5
// speedup vs baseline: 1.6878x; 1.2727x over previous
#include <cuda_runtime.h>
#include <cstdint>

// SSIM loss: fused separable 11x11 Gaussian SSIM.
// 4-channel trick: SSIM only needs blur(x), blur(y), blur(x^2+y^2), blur(xy)
// -> exactly two packed f32x2 channels. imgs (16,3,512,512) fp32 -> scalar.

#define IMG     512
#define NIMG    48
#define TX      64
#define TY      32
#define IW      74              // TX + 10
#define RAWP    75              // raw pair-row stride
#define IH      42              // TY + 10
#define HS      65              // H row stride (in u64 pairs)
#define NT      352             // 11 warps
#define GXB     8
#define GYB     16
#define NBLOCKS (GXB*GYB*NIMG)  // 6144
#define SMEM_FLOATS 10920       // 43680 bytes = 2 planes * 42*65 u64

#define W0f 0.00102838f
#define W1f 0.00759876f
#define W2f 0.03600077f
#define W3f 0.10936070f
#define W4f 0.21300554f
#define W5f 0.26601173f

__device__ float    g_partials[NBLOCKS];
__device__ unsigned g_sync = 0;

__device__ __forceinline__ uint64_t bc(float w) {
    unsigned u = __float_as_uint(w);
    return ((uint64_t)u << 32) | u;
}
__device__ __forceinline__ void f2fma(uint64_t& d, uint64_t a, uint64_t b) {
    asm("fma.rn.f32x2 %0,%1,%2,%0;" : "+l"(d) : "l"(a), "l"(b));
}
__device__ __forceinline__ uint64_t pack2(float lo, float hi) {
    uint64_t r; asm("mov.b64 %0,{%1,%2};" : "=l"(r) : "r"(__float_as_uint(lo)), "r"(__float_as_uint(hi)));
    return r;
}
__device__ __forceinline__ float lo32(uint64_t u) { return __uint_as_float((unsigned)u); }
__device__ __forceinline__ float hi32(uint64_t u) { return __uint_as_float((unsigned)(u >> 32)); }

// Vertical blur strip of LEN rows + pointwise SSIM.
// Planes: H01 (mu-pairs) at S[0], Hsp (s=x2+y2, p=xy pairs) at S[5460].
template<int LEN>
__device__ __forceinline__ float vstrip(const float* __restrict__ S, int rs, int col,
                                        const uint64_t (&Wb)[6])
{
    const uint64_t* H01 = (const uint64_t*)S;
    const uint64_t* Hsp = (const uint64_t*)(S + 5460);
    const int base = rs * HS + col;

    uint64_t b01[LEN], bsp[LEN];
    #pragma unroll
    for (int o = 0; o < LEN; o++) { b01[o] = 0ull; bsp[o] = 0ull; }

    #pragma unroll
    for (int e = 0; e < LEN + 10; e++) {
        uint64_t f01 = H01[base + e * HS];
        uint64_t fsp = Hsp[base + e * HS];
        #pragma unroll
        for (int o = 0; o < LEN; o++) {
            const int d = e - o;
            if (d >= 0 && d < 11) {
                const int wi = (d < 6) ? d : 10 - d;
                f2fma(b01[o], Wb[wi], f01);
                f2fma(bsp[o], Wb[wi], fsp);
            }
        }
    }

    const float C1 = 1e-4f, C2 = 9e-4f;
    float acc = 0.f;
    #pragma unroll
    for (int o = 0; o < LEN; o++) {
        float mu1 = lo32(b01[o]), mu2 = hi32(b01[o]);
        float Sb  = lo32(bsp[o]), Pb  = hi32(bsp[o]);
        float mu1sq = mu1 * mu1;
        float musum = fmaf(mu2, mu2, mu1sq);      // mu1^2 + mu2^2
        float mu12  = mu1 * mu2;
        float sg12  = Pb - mu12;                  // sigma12
        float sgsum = Sb - musum;                 // sigma1^2 + sigma2^2
        float num = fmaf(2.0f, mu12, C1) * fmaf(2.0f, sg12, C2);
        float den = (musum + C1) * (sgsum + C2);
        acc += __fdividef(num, den);
    }
    return acc;
}

__global__ __launch_bounds__(NT, 4)
void ssim_kernel(const float* __restrict__ img1,
                 const float* __restrict__ img2,
                 float* __restrict__ out)
{
    extern __shared__ float S[];
    const int tid = threadIdx.x;
    const int bz  = blockIdx.z;
    const float* ib1 = img1 + (size_t)bz * IMG * IMG;
    const float* ib2 = img2 + (size_t)bz * IMG * IMG;
    const int gx0 = blockIdx.x * TX - 5;
    const int gy0 = blockIdx.y * TY - 5;

    const uint64_t Wb[6] = { bc(W0f), bc(W1f), bc(W2f), bc(W3f), bc(W4f), bc(W5f) };
    const float Wt[11] = {W0f, W1f, W2f, W3f, W4f, W5f, W4f, W3f, W2f, W1f, W0f};
    (void)Wt;

    // ---- stage 0: load raw (x,y) pairs into smem, zero-padded ----
    float2* raw = (float2*)S;
    for (int idx = tid; idx < IH * IW; idx += NT) {
        int r = idx / IW;
        int c = idx - r * IW;
        int gy = gy0 + r;
        int gx = gx0 + c;
        bool ok = ((unsigned)gy < (unsigned)IMG) & ((unsigned)gx < (unsigned)IMG);
        int g = gy * IMG + gx;
        float x = ok ? __ldg(ib1 + g) : 0.0f;
        float y = ok ? __ldg(ib2 + g) : 0.0f;
        raw[r * RAWP + c] = make_float2(x, y);
    }
    __syncthreads();

    // ---- pass 1: horizontal blur of 2 packed channels, strips of 8 cols ----
    uint64_t a01[8], asp[8];
    const bool p1act = (tid < IH * 8);
    int p1row = 0, p1cs = 0;
    if (p1act) {
        p1row = tid % IH;
        p1cs  = (tid / IH) * 8;
        const uint64_t* rp = (const uint64_t*)S + p1row * RAWP + p1cs;
        #pragma unroll
        for (int o = 0; o < 8; o++) { a01[o] = 0ull; asp[o] = 0ull; }
        #pragma unroll
        for (int e = 0; e < 18; e++) {
            uint64_t xy = rp[e];
            float x = lo32(xy), y = hi32(xy);
            float s = fmaf(y, y, x * x);
            float p = x * y;
            uint64_t sp = pack2(s, p);
            #pragma unroll
            for (int o = 0; o < 8; o++) {
                const int d = e - o;
                if (d >= 0 && d < 11) {
                    const int wi = (d < 6) ? d : 10 - d;
                    f2fma(a01[o], Wb[wi], xy);
                    f2fma(asp[o], Wb[wi], sp);
                }
            }
        }
    }
    __syncthreads();            // all raw reads complete before H overwrites raw
    if (p1act) {
        uint64_t* H01 = (uint64_t*)S;
        uint64_t* Hsp = (uint64_t*)(S + 5460);
        const int hb = p1row * HS + p1cs;
        #pragma unroll
        for (int o = 0; o < 8; o++) {
            H01[hb + o] = a01[o];
            Hsp[hb + o] = asp[o];
        }
    }
    __syncthreads();

    // ---- pass 2: vertical blur + SSIM; 320 strips = 64 cols x {7,7,6,6,6} ----
    float acc = 0.f;
    {
        const int col = tid & 63;
        const int seg = tid >> 6;           // warp-uniform
        if (seg < 2)      acc = vstrip<7>(S, seg * 7, col, Wb);
        else if (seg < 5) acc = vstrip<6>(S, 14 + (seg - 2) * 6, col, Wb);
    }

    // ---- block reduction ----
    #pragma unroll
    for (int off = 16; off > 0; off >>= 1)
        acc += __shfl_xor_sync(0xFFFFFFFFu, acc, off);

    __shared__ float warpsum[NT / 32];
    if ((tid & 31) == 0) warpsum[tid >> 5] = acc;
    __syncthreads();

    __shared__ bool is_last;
    if (tid == 0) {
        float s = 0.f;
        #pragma unroll
        for (int i = 0; i < NT / 32; i++) s += warpsum[i];
        int bid = blockIdx.x + GXB * (blockIdx.y + GYB * bz);
        g_partials[bid] = s;
        __threadfence();
        unsigned prev = atomicAdd(&g_sync, 1u);
        is_last = (prev == NBLOCKS - 1);
    }
    __syncthreads();

    // ---- last block: deterministic final reduction ----
    if (is_last) {
        __threadfence();
        __shared__ double sd[NT];
        double s = 0.0;
        for (int k = tid; k < NBLOCKS; k += NT)
            s += (double)g_partials[k];
        sd[tid] = s;
        __syncthreads();
        if (tid < 96) sd[tid] += sd[tid + 256];
        __syncthreads();
        #pragma unroll
        for (int st = 128; st > 0; st >>= 1) {
            if (tid < st) sd[tid] += sd[tid + st];
            __syncthreads();
        }
        if (tid == 0) {
            const double N = 16.0 * 3.0 * 512.0 * 512.0;
            out[0] = (float)(1.0 - sd[0] / N);
            g_sync = 0;     // reset for next graph replay
        }
    }
}

extern "C" void kernel_launch(void* const* d_in, const int* in_sizes, int n_in,
                              void* d_out, int out_size)
{
    const float* img1 = (const float*)d_in[0];
    const float* img2 = (const float*)d_in[1];
    float* out = (float*)d_out;

    const int smem_bytes = SMEM_FLOATS * (int)sizeof(float);   // 43680
    cudaFuncSetAttribute(ssim_kernel,
                         cudaFuncAttributeMaxDynamicSharedMemorySize, smem_bytes);

    dim3 grid(GXB, GYB, NIMG);
    ssim_kernel<<<grid, NT, smem_bytes>>>(img1, img2, out);
}

// round 6
// speedup vs baseline: 1.9507x; 1.1557x over previous
#include <cuda_runtime.h>
#include <cstdint>

// SSIM loss: fused separable 11x11 Gaussian, V-first (gmem-direct, no staging).
// Channels: SSIM needs only blur(x), blur(y), blur(x^2+y^2), blur(xy)
// -> two packed f32x2 channels. imgs (16,3,512,512) fp32 -> scalar.

#define IMG     512
#define NIMG    48
#define TX      64
#define TY      32
#define COLS    74              // TX + 10
#define VP      75              // V plane row stride in u64
#define NT      352             // 11 warps
#define GXB     8
#define GYB     16
#define NBLOCKS (GXB*GYB*NIMG)  // 6144
#define SMEM_U64 (2*TY*VP)      // 4800 u64 = 38400 B

#define W0f 0.00102838f
#define W1f 0.00759876f
#define W2f 0.03600077f
#define W3f 0.10936070f
#define W4f 0.21300554f
#define W5f 0.26601173f

__device__ float    g_partials[NBLOCKS];
__device__ unsigned g_sync = 0;

__device__ __forceinline__ uint64_t bc(float w) {
    unsigned u = __float_as_uint(w);
    return ((uint64_t)u << 32) | u;
}
__device__ __forceinline__ void f2fma(uint64_t& d, uint64_t a, uint64_t b) {
    asm("fma.rn.f32x2 %0,%1,%2,%0;" : "+l"(d) : "l"(a), "l"(b));
}
__device__ __forceinline__ uint64_t pack2(float lo, float hi) {
    uint64_t r; asm("mov.b64 %0,{%1,%2};" : "=l"(r) : "r"(__float_as_uint(lo)), "r"(__float_as_uint(hi)));
    return r;
}
__device__ __forceinline__ float lo32(uint64_t u) { return __uint_as_float((unsigned)u); }
__device__ __forceinline__ float hi32(uint64_t u) { return __uint_as_float((unsigned)(u >> 32)); }

// Horizontal blur strip of LEN output cols + pointwise SSIM.
template<int LEN>
__device__ __forceinline__ float hstrip(const uint64_t* __restrict__ S, int row, int cs,
                                        const uint64_t (&Wb)[6])
{
    const int base = row * VP + cs;
    uint64_t b01[LEN], bsp[LEN];
    #pragma unroll
    for (int o = 0; o < LEN; o++) { b01[o] = 0ull; bsp[o] = 0ull; }

    #pragma unroll
    for (int e = 0; e < LEN + 10; e++) {
        uint64_t f01 = S[base + e];
        uint64_t fsp = S[2*TY*VP/2 + base + e];   // second plane at offset TY*VP
        #pragma unroll
        for (int o = 0; o < LEN; o++) {
            const int d = e - o;
            if (d >= 0 && d < 11) {
                const int wi = (d < 6) ? d : 10 - d;
                f2fma(b01[o], Wb[wi], f01);
                f2fma(bsp[o], Wb[wi], fsp);
            }
        }
    }

    const float C1 = 1e-4f, C2 = 9e-4f;
    float acc = 0.f;
    #pragma unroll
    for (int o = 0; o < LEN; o++) {
        float mu1 = lo32(b01[o]), mu2 = hi32(b01[o]);
        float Sb  = lo32(bsp[o]), Pb  = hi32(bsp[o]);
        float mu1sq = mu1 * mu1;
        float musum = fmaf(mu2, mu2, mu1sq);
        float mu12  = mu1 * mu2;
        float sg12  = Pb - mu12;
        float sgsum = Sb - musum;
        float num = fmaf(2.0f, mu12, C1) * fmaf(2.0f, sg12, C2);
        float den = (musum + C1) * (sgsum + C2);
        acc += __fdividef(num, den);
    }
    return acc;
}

__global__ __launch_bounds__(NT, 4)
void ssim_kernel(const float* __restrict__ img1,
                 const float* __restrict__ img2,
                 float* __restrict__ out)
{
    extern __shared__ uint64_t S[];   // V01 plane [TY][VP], Vsp plane [TY][VP]
    const int tid = threadIdx.x;
    const int bz  = blockIdx.z;
    const float* ib1 = img1 + (size_t)bz * IMG * IMG;
    const float* ib2 = img2 + (size_t)bz * IMG * IMG;
    const int gx0 = blockIdx.x * TX - 5;
    const int gy0 = blockIdx.y * TY - 5;

    const uint64_t Wb[6] = { bc(W0f), bc(W1f), bc(W2f), bc(W3f), bc(W4f), bc(W5f) };

    // ---- pass V: vertical blur straight from gmem (coalesced: lane = column) ----
    // 296 strips = 74 cols x 4 row-strips of 8 outputs.
    if (tid < COLS * 4) {
        int s = tid / COLS;               // 0..3
        int c = tid - s * COLS;           // 0..73
        int gx = gx0 + c;
        bool colok = (unsigned)gx < (unsigned)IMG;
        int r0 = s * 8;

        uint64_t a01[8], asp[8];
        #pragma unroll
        for (int o = 0; o < 8; o++) { a01[o] = 0ull; asp[o] = 0ull; }

        #pragma unroll
        for (int e = 0; e < 18; e++) {
            int gy = gy0 + r0 + e;
            bool ok = colok & ((unsigned)gy < (unsigned)IMG);
            int g = gy * IMG + gx;
            float x = ok ? __ldg(ib1 + g) : 0.0f;
            float y = ok ? __ldg(ib2 + g) : 0.0f;
            uint64_t xy = pack2(x, y);
            uint64_t sp = pack2(fmaf(y, y, x * x), x * y);
            #pragma unroll
            for (int o = 0; o < 8; o++) {
                const int d = e - o;
                if (d >= 0 && d < 11) {
                    const int wi = (d < 6) ? d : 10 - d;
                    f2fma(a01[o], Wb[wi], xy);
                    f2fma(asp[o], Wb[wi], sp);
                }
            }
        }
        #pragma unroll
        for (int o = 0; o < 8; o++) {
            S[(r0 + o) * VP + c]           = a01[o];
            S[TY * VP + (r0 + o) * VP + c] = asp[o];
        }
    }
    __syncthreads();

    // ---- pass H: horizontal blur + SSIM; 352 strips = 32 rows x (9x6 + 2x5) cols ----
    float acc;
    {
        const int row = tid & 31;
        const int g   = tid >> 5;         // 0..10, warp-uniform
        if (g < 9) acc = hstrip<6>(S, row, g * 6, Wb);
        else       acc = hstrip<5>(S, row, 54 + (g - 9) * 5, Wb);
    }

    // ---- block reduction ----
    #pragma unroll
    for (int off = 16; off > 0; off >>= 1)
        acc += __shfl_xor_sync(0xFFFFFFFFu, acc, off);

    __shared__ float warpsum[NT / 32];
    if ((tid & 31) == 0) warpsum[tid >> 5] = acc;
    __syncthreads();

    __shared__ bool is_last;
    if (tid == 0) {
        float s = 0.f;
        #pragma unroll
        for (int i = 0; i < NT / 32; i++) s += warpsum[i];
        int bid = blockIdx.x + GXB * (blockIdx.y + GYB * bz);
        g_partials[bid] = s;
        __threadfence();
        unsigned prev = atomicAdd(&g_sync, 1u);
        is_last = (prev == NBLOCKS - 1);
    }
    __syncthreads();

    // ---- last block: deterministic final reduction ----
    if (is_last) {
        __threadfence();
        __shared__ double sd[NT];
        double s = 0.0;
        for (int k = tid; k < NBLOCKS; k += NT)
            s += (double)g_partials[k];
        sd[tid] = s;
        __syncthreads();
        if (tid < 96) sd[tid] += sd[tid + 256];
        __syncthreads();
        #pragma unroll
        for (int st = 128; st > 0; st >>= 1) {
            if (tid < st) sd[tid] += sd[tid + st];
            __syncthreads();
        }
        if (tid == 0) {
            const double N = 16.0 * 3.0 * 512.0 * 512.0;
            out[0] = (float)(1.0 - sd[0] / N);
            g_sync = 0;     // reset for next graph replay
        }
    }
}

extern "C" void kernel_launch(void* const* d_in, const int* in_sizes, int n_in,
                              void* d_out, int out_size)
{
    const float* img1 = (const float*)d_in[0];
    const float* img2 = (const float*)d_in[1];
    float* out = (float*)d_out;

    const int smem_bytes = SMEM_U64 * (int)sizeof(uint64_t);   // 38400
    cudaFuncSetAttribute(ssim_kernel,
                         cudaFuncAttributeMaxDynamicSharedMemorySize, smem_bytes);

    dim3 grid(GXB, GYB, NIMG);
    ssim_kernel<<<grid, NT, smem_bytes>>>(img1, img2, out);
}

// round 7
// speedup vs baseline: 1.9606x; 1.0051x over previous
#include <cuda_runtime.h>
#include <cstdint>

// SSIM loss: fused separable 11x11 Gaussian, V-first, interleaved smem planes.
// Channels: blur(x), blur(y), blur(x^2+y^2), blur(xy) -> two packed f32x2.
// imgs (16,3,512,512) fp32 -> scalar fp32 = 1 - mean(ssim_map).

#define IMG     512
#define NIMG    48
#define TX      64
#define TY      32
#define COLS    74              // TX + 10
#define VP      75              // V plane row stride in ulonglong2 elements
#define NT      352             // 11 warps
#define GXB     8
#define GYB     16
#define NBLOCKS (GXB*GYB*NIMG)  // 6144
#define SMEM_BYTES (TY*VP*16)   // 38400

#define W0f 0.00102838f
#define W1f 0.00759876f
#define W2f 0.03600077f
#define W3f 0.10936070f
#define W4f 0.21300554f
#define W5f 0.26601173f

__device__ float    g_partials[NBLOCKS];
__device__ unsigned g_sync = 0;

__device__ __forceinline__ uint64_t bc(float w) {
    unsigned u = __float_as_uint(w);
    return ((uint64_t)u << 32) | u;
}
__device__ __forceinline__ void f2fma(uint64_t& d, uint64_t a, uint64_t b) {
    asm("fma.rn.f32x2 %0,%1,%2,%0;" : "+l"(d) : "l"(a), "l"(b));
}
__device__ __forceinline__ uint64_t pack2(float lo, float hi) {
    uint64_t r; asm("mov.b64 %0,{%1,%2};" : "=l"(r) : "r"(__float_as_uint(lo)), "r"(__float_as_uint(hi)));
    return r;
}
__device__ __forceinline__ float lo32(uint64_t u) { return __uint_as_float((unsigned)u); }
__device__ __forceinline__ float hi32(uint64_t u) { return __uint_as_float((unsigned)(u >> 32)); }

// Vertical accumulation body; CHECK=true adds per-row bounds predication.
template<bool CHECK>
__device__ __forceinline__ void vbody(const float* __restrict__ p1,
                                      const float* __restrict__ p2,
                                      int gy_first,
                                      uint64_t (&a01)[8], uint64_t (&asp)[8],
                                      const uint64_t (&Wb)[6])
{
    #pragma unroll
    for (int e = 0; e < 18; e++) {
        float x, y;
        if (CHECK) {
            bool ok = (unsigned)(gy_first + e) < (unsigned)IMG;
            x = ok ? __ldg(p1 + e * IMG) : 0.0f;
            y = ok ? __ldg(p2 + e * IMG) : 0.0f;
        } else {
            x = __ldg(p1 + e * IMG);
            y = __ldg(p2 + e * IMG);
        }
        uint64_t xy = pack2(x, y);
        uint64_t sp = pack2(fmaf(y, y, x * x), x * y);
        #pragma unroll
        for (int o = 0; o < 8; o++) {
            const int d = e - o;
            if (d >= 0 && d < 11) {
                const int wi = (d < 6) ? d : 10 - d;
                f2fma(a01[o], Wb[wi], xy);
                f2fma(asp[o], Wb[wi], sp);
            }
        }
    }
}

// Horizontal blur strip of LEN output cols + pointwise SSIM.
template<int LEN>
__device__ __forceinline__ float hstrip(const ulonglong2* __restrict__ S, int row, int cs,
                                        const uint64_t (&Wb)[6])
{
    const ulonglong2* p = S + row * VP + cs;
    uint64_t b01[LEN], bsp[LEN];
    #pragma unroll
    for (int o = 0; o < LEN; o++) { b01[o] = 0ull; bsp[o] = 0ull; }

    #pragma unroll
    for (int e = 0; e < LEN + 10; e++) {
        ulonglong2 f = p[e];                 // one LDS.128: both planes
        #pragma unroll
        for (int o = 0; o < LEN; o++) {
            const int d = e - o;
            if (d >= 0 && d < 11) {
                const int wi = (d < 6) ? d : 10 - d;
                f2fma(b01[o], Wb[wi], f.x);
                f2fma(bsp[o], Wb[wi], f.y);
            }
        }
    }

    const float C1 = 1e-4f, C2 = 9e-4f;
    float acc = 0.f;
    #pragma unroll
    for (int o = 0; o < LEN; o++) {
        float mu1 = lo32(b01[o]), mu2 = hi32(b01[o]);
        float Sb  = lo32(bsp[o]), Pb  = hi32(bsp[o]);
        float mu1sq = mu1 * mu1;
        float musum = fmaf(mu2, mu2, mu1sq);
        float mu12  = mu1 * mu2;
        float sg12  = Pb - mu12;
        float sgsum = Sb - musum;
        float num = fmaf(2.0f, mu12, C1) * fmaf(2.0f, sg12, C2);
        float den = (musum + C1) * (sgsum + C2);
        acc += __fdividef(num, den);
    }
    return acc;
}

__global__ __launch_bounds__(NT, 4)
void ssim_kernel(const float* __restrict__ img1,
                 const float* __restrict__ img2,
                 float* __restrict__ out)
{
    extern __shared__ ulonglong2 S[];   // [TY][VP] interleaved (v01, vsp)
    const int tid = threadIdx.x;
    const int bz  = blockIdx.z;
    const float* ib1 = img1 + (size_t)bz * IMG * IMG;
    const float* ib2 = img2 + (size_t)bz * IMG * IMG;
    const int gx0 = blockIdx.x * TX - 5;
    const int gy0 = blockIdx.y * TY - 5;

    const uint64_t Wb[6] = { bc(W0f), bc(W1f), bc(W2f), bc(W3f), bc(W4f), bc(W5f) };

    // ---- pass V: vertical blur straight from gmem (lane = column, coalesced) ----
    // 296 strips = 74 cols x 4 row-strips of 8 outputs.
    if (tid < COLS * 4) {
        int s = tid / COLS;               // 0..3
        int c = tid - s * COLS;           // 0..73
        int gx = gx0 + c;
        int r0 = s * 8;

        uint64_t a01[8], asp[8];
        #pragma unroll
        for (int o = 0; o < 8; o++) { a01[o] = 0ull; asp[o] = 0ull; }

        if ((unsigned)gx < (unsigned)IMG) {
            const int gy_first = gy0 + r0;
            const float* p1 = ib1 + (size_t)gy_first * IMG + gx;
            const float* p2 = ib2 + (size_t)gy_first * IMG + gx;
            const bool rowsafe = (gy0 >= 0) & (gy0 + 41 < IMG);  // block-uniform
            if (rowsafe) vbody<false>(p1, p2, gy_first, a01, asp, Wb);
            else         vbody<true >(p1, p2, gy_first, a01, asp, Wb);
        }
        #pragma unroll
        for (int o = 0; o < 8; o++)
            S[(r0 + o) * VP + c] = make_ulonglong2(a01[o], asp[o]);  // STS.128
    }
    __syncthreads();

    // ---- pass H: horizontal blur + SSIM; 352 strips = 32 rows x (9x6 + 2x5) ----
    float acc;
    {
        const int row = tid & 31;
        const int g   = tid >> 5;         // 0..10, warp-uniform
        if (g < 9) acc = hstrip<6>(S, row, g * 6, Wb);
        else       acc = hstrip<5>(S, row, 54 + (g - 9) * 5, Wb);
    }

    // ---- block reduction ----
    #pragma unroll
    for (int off = 16; off > 0; off >>= 1)
        acc += __shfl_xor_sync(0xFFFFFFFFu, acc, off);

    __shared__ float warpsum[NT / 32];
    if ((tid & 31) == 0) warpsum[tid >> 5] = acc;
    __syncthreads();

    __shared__ bool is_last;
    if (tid == 0) {
        float s = 0.f;
        #pragma unroll
        for (int i = 0; i < NT / 32; i++) s += warpsum[i];
        int bid = blockIdx.x + GXB * (blockIdx.y + GYB * bz);
        g_partials[bid] = s;
        __threadfence();
        unsigned prev = atomicAdd(&g_sync, 1u);
        is_last = (prev == NBLOCKS - 1);
    }
    __syncthreads();

    // ---- last block: deterministic final reduction ----
    if (is_last) {
        __threadfence();
        __shared__ double sd[NT];
        double s = 0.0;
        for (int k = tid; k < NBLOCKS; k += NT)
            s += (double)g_partials[k];
        sd[tid] = s;
        __syncthreads();
        if (tid < 96) sd[tid] += sd[tid + 256];
        __syncthreads();
        #pragma unroll
        for (int st = 128; st > 0; st >>= 1) {
            if (tid < st) sd[tid] += sd[tid + st];
            __syncthreads();
        }
        if (tid == 0) {
            const double N = 16.0 * 3.0 * 512.0 * 512.0;
            out[0] = (float)(1.0 - sd[0] / N);
            g_sync = 0;     // reset for next graph replay
        }
    }
}

extern "C" void kernel_launch(void* const* d_in, const int* in_sizes, int n_in,
                              void* d_out, int out_size)
{
    const float* img1 = (const float*)d_in[0];
    const float* img2 = (const float*)d_in[1];
    float* out = (float*)d_out;

    cudaFuncSetAttribute(ssim_kernel,
                         cudaFuncAttributeMaxDynamicSharedMemorySize, SMEM_BYTES);

    dim3 grid(GXB, GYB, NIMG);
    ssim_kernel<<<grid, NT, SMEM_BYTES>>>(img1, img2, out);
}